// round 2
// baseline (speedup 1.0000x reference)
#include <cuda_runtime.h>
#include <math.h>
#include <stdint.h>

#define LSEQ 50
#define BATCH 256
#define DIN 256
#define LAT 512
#define HODE 1024
#define HID 1024
#define G3 3072
#define ROWSTRIDE 257   // D_IN + 1 (dt column appended)

// ---------------- scratch (device globals; no allocation allowed) ----------------
__device__ float g_act[BATCH * HODE];                 // tanh(y@W1+b1)
__device__ float g_hcatA[BATCH * HID];                // carry buffer A: [:,0:512]=y, [:,512:1024]=gru_state
__device__ float g_hcatB[BATCH * HID];                // carry buffer B
__device__ float g_gh[BATCH * G3];                    // hcat @ Whh^T + bhh (per step)
__device__ float g_gi[(size_t)LSEQ * BATCH * G3];     // x @ Wih^T + bih (ALL steps, precomputed)

// ---------------- generic fp32 tiled GEMM: C = epi(A*B + bias) ----------------
// A: [M,K] row-major with stride lda.
// TRANSB=false: B is [K,N] row-major (ldb = row stride). C[m][n]=sum A[m][k]*B[k][n]
// TRANSB=true : B is [N,K] row-major (ldb = row stride). C[m][n]=sum A[m][k]*B[n][k]
// epi 0: C = acc + bias
// epi 1: C = tanhf(acc + bias)
// epi 2: C += (acc + bias) * (hstep_base[m*257] / 3)   (Euler ODE update, in place)
// All dims are multiples of the tile sizes for this problem (no bounds checks).
constexpr int BM = 64, BN = 64, BK = 16;

template <bool TRANSB>
__global__ __launch_bounds__(256)
void gemm_k(const float* __restrict__ A, int lda,
            const float* __restrict__ B, int ldb,
            const float* __restrict__ bias,
            float* __restrict__ C, int ldc,
            int K, int epi, const float* __restrict__ hstep_base)
{
    __shared__ float As[BK][BM + 4];   // [k][m], padded: row stride 68 floats (16B aligned)
    __shared__ float Bs[BK][BN + 4];   // [k][n]

    const int tid  = threadIdx.x;
    const int bm   = blockIdx.y * BM;
    const int bn   = blockIdx.x * BN;
    const int tcol = tid & 15;         // 16 col-groups of 4
    const int trow = tid >> 4;         // 16 row-groups of 4

    float acc[4][4];
#pragma unroll
    for (int i = 0; i < 4; i++)
#pragma unroll
        for (int j = 0; j < 4; j++) acc[i][j] = 0.0f;

    const int atx = tid & 15;          // k index within tile
    const int aty = tid >> 4;          // row index base

    for (int k0 = 0; k0 < K; k0 += BK) {
        // --- load A tile (transposed into As[k][m]) ---
#pragma unroll
        for (int p = 0; p < 4; p++) {
            int m = aty + p * 16;
            As[atx][m] = A[(size_t)(bm + m) * lda + (k0 + atx)];
        }
        // --- load B tile into Bs[k][n] ---
        if (!TRANSB) {
            int btx = tid & 63;        // n
            int bty = tid >> 6;        // k base
#pragma unroll
            for (int p = 0; p < 4; p++) {
                int kk = bty + p * 4;
                Bs[kk][btx] = B[(size_t)(k0 + kk) * ldb + (bn + btx)];
            }
        } else {
#pragma unroll
            for (int p = 0; p < 4; p++) {
                int n = aty + p * 16;
                Bs[atx][n] = B[(size_t)(bn + n) * ldb + (k0 + atx)];
            }
        }
        __syncthreads();

#pragma unroll
        for (int k = 0; k < BK; k++) {
            float4 a = *reinterpret_cast<const float4*>(&As[k][trow * 4]);
            float4 b = *reinterpret_cast<const float4*>(&Bs[k][tcol * 4]);
            acc[0][0] += a.x * b.x; acc[0][1] += a.x * b.y; acc[0][2] += a.x * b.z; acc[0][3] += a.x * b.w;
            acc[1][0] += a.y * b.x; acc[1][1] += a.y * b.y; acc[1][2] += a.y * b.z; acc[1][3] += a.y * b.w;
            acc[2][0] += a.z * b.x; acc[2][1] += a.z * b.y; acc[2][2] += a.z * b.z; acc[2][3] += a.z * b.w;
            acc[3][0] += a.w * b.x; acc[3][1] += a.w * b.y; acc[3][2] += a.w * b.z; acc[3][3] += a.w * b.w;
        }
        __syncthreads();
    }

    // ---------------- epilogue ----------------
    float bv[4];
#pragma unroll
    for (int j = 0; j < 4; j++) bv[j] = bias[bn + tcol * 4 + j];

#pragma unroll
    for (int i = 0; i < 4; i++) {
        int m = bm + trow * 4 + i;
        float* crow = C + (size_t)m * ldc + bn + tcol * 4;
        if (epi == 0) {
#pragma unroll
            for (int j = 0; j < 4; j++) crow[j] = acc[i][j] + bv[j];
        } else if (epi == 1) {
#pragma unroll
            for (int j = 0; j < 4; j++) crow[j] = tanhf(acc[i][j] + bv[j]);
        } else {
            float h = hstep_base[m * ROWSTRIDE] * (1.0f / 3.0f);
#pragma unroll
            for (int j = 0; j < 4; j++) crow[j] += (acc[i][j] + bv[j]) * h;
        }
    }
}

// ---------------- GRU gates + carry update + output ----------------
// gi, gh: [256, 3072]; cur: current hcat [256,1024]; nxt: next hcat.
// new_h = (1-z)*n + z*hcat ; next carry halves BOTH = new_h[:, :512].
__global__ __launch_bounds__(1024)
void gate_k(const float* __restrict__ gi, const float* __restrict__ gh,
            const float* __restrict__ cur, float* __restrict__ nxt,
            float* __restrict__ out_seq, float* __restrict__ out_tail)
{
    int m = blockIdx.x;
    int j = threadIdx.x;   // 0..1023
    size_t base = (size_t)m * G3;

    float gr = gi[base + j]            + gh[base + j];
    float gz = gi[base + HID + j]      + gh[base + HID + j];
    float r  = 1.0f / (1.0f + expf(-gr));
    float z  = 1.0f / (1.0f + expf(-gz));
    float n  = tanhf(gi[base + 2 * HID + j] + r * gh[base + 2 * HID + j]);
    float h  = cur[m * HID + j];
    float nh = (1.0f - z) * n + z * h;

    out_tail[m * HID + j] = nh;                 // last step's write survives
    if (j < LAT) {
        out_seq[m * LAT + j] = nh;              // ode_states_post[t]
        nxt[m * HID + j]       = nh;            // next ode_state
        nxt[m * HID + LAT + j] = nh;            // next gru_state (same slice per reference)
    }
}

__global__ void zero_k(float* __restrict__ p, int n)
{
    int i = blockIdx.x * blockDim.x + threadIdx.x;
    if (i < n) p[i] = 0.0f;
}

// ---------------- launch ----------------
extern "C" void kernel_launch(void* const* d_in, const int* in_sizes, int n_in,
                              void* d_out, int out_size)
{
    const float* data = (const float*)d_in[0];   // (50, 256, 257)
    const float* w1   = (const float*)d_in[1];   // (512, 1024)
    const float* b1   = (const float*)d_in[2];   // (1024,)
    const float* w2   = (const float*)d_in[3];   // (1024, 512)
    const float* b2   = (const float*)d_in[4];   // (512,)
    const float* wih  = (const float*)d_in[5];   // (3072, 256)
    const float* bih  = (const float*)d_in[6];   // (3072,)
    const float* whh  = (const float*)d_in[7];   // (3072, 1024)
    const float* bhh  = (const float*)d_in[8];   // (3072,)

    float* out      = (float*)d_out;
    float* out_tail = out + (size_t)LSEQ * BATCH * LAT;

    float *act, *hcatA, *hcatB, *gh, *gi;
    cudaGetSymbolAddress((void**)&act,   g_act);
    cudaGetSymbolAddress((void**)&hcatA, g_hcatA);
    cudaGetSymbolAddress((void**)&hcatB, g_hcatB);
    cudaGetSymbolAddress((void**)&gh,    g_gh);
    cudaGetSymbolAddress((void**)&gi,    g_gi);

    // zero-init carry (must be re-done every replay)
    zero_k<<<(BATCH * HID + 255) / 256, 256>>>(hcatA, BATCH * HID);

    // Precompute gi for ALL steps: [12800,256] x Wih^T -> [12800,3072]
    {
        dim3 grid(G3 / BN, (LSEQ * BATCH) / BM);
        gemm_k<true><<<grid, 256>>>(data, ROWSTRIDE, wih, DIN, bih, gi, G3, DIN, 0, nullptr);
    }

    for (int t = 0; t < LSEQ; t++) {
        float* cur = (t & 1) ? hcatB : hcatA;
        float* nxt = (t & 1) ? hcatA : hcatB;
        const float* hstep = data + (size_t)t * BATCH * ROWSTRIDE + DIN;

        // 3 Euler substeps: y (= cur[:, :512], in place)
        for (int s = 0; s < 3; s++) {
            dim3 g1(HODE / BN, BATCH / BM);    // (16,4)
            gemm_k<false><<<g1, 256>>>(cur, HID, w1, HODE, b1, act, HODE, LAT, 1, nullptr);
            dim3 g2(LAT / BN, BATCH / BM);     // (8,4)
            gemm_k<false><<<g2, 256>>>(act, HODE, w2, LAT, b2, cur, HID, HODE, 2, hstep);
        }

        // gh = hcat @ Whh^T + bhh   [256,1024] x [3072,1024]^T
        {
            dim3 g4(G3 / BN, BATCH / BM);      // (48,4)
            gemm_k<true><<<g4, 256>>>(cur, HID, whh, HID, bhh, gh, G3, HID, 0, nullptr);
        }

        // gates + carry + outputs
        gate_k<<<BATCH, HID>>>(gi + (size_t)t * BATCH * G3, gh, cur, nxt,
                               out + (size_t)t * BATCH * LAT, out_tail);
    }
}

// round 3
// speedup vs baseline: 1.8358x; 1.8358x over previous
#include <cuda_runtime.h>
#include <math.h>
#include <stdint.h>

#define LSEQ 50
#define BATCH 256
#define DIN 256
#define LAT 512
#define HODE 1024
#define HID 1024
#define G3 3072
#define ROWSTRIDE 257   // D_IN + 1 (dt column appended)

// ---------------- scratch (device globals; no allocation allowed) ----------------
__device__ float g_act[BATCH * HODE];                 // tanh(y@W1+b1)
__device__ float g_hcatA[BATCH * HID];                // carry A: [:,0:512]=y, [:,512:1024]=gru_state
__device__ float g_hcatB[BATCH * HID];                // carry B
__device__ float g_gh[BATCH * G3];                    // hcat @ Whh^T + bhh (per step)
__device__ float g_gi[(size_t)LSEQ * BATCH * G3];     // x @ Wih^T + bih (ALL steps, precomputed)

// ---------------- TF32 helpers ----------------
__device__ __forceinline__ float to_tf32(float x) {
    float r;
    asm("cvt.rna.tf32.f32 %0, %1;" : "=f"(r) : "f"(x));
    return r;
}

__device__ __forceinline__ void mma_tf32(float& c0, float& c1, float& c2, float& c3,
                                         uint32_t a0, uint32_t a1, uint32_t a2, uint32_t a3,
                                         uint32_t b0, uint32_t b1) {
    asm volatile(
        "mma.sync.aligned.m16n8k8.row.col.f32.tf32.tf32.f32 "
        "{%0,%1,%2,%3}, {%4,%5,%6,%7}, {%8,%9}, {%0,%1,%2,%3};"
        : "+f"(c0), "+f"(c1), "+f"(c2), "+f"(c3)
        : "r"(a0), "r"(a1), "r"(a2), "r"(a3), "r"(b0), "r"(b1));
}

// ---------------- TF32 tensor-core GEMM ----------------
// CTA tile 64x64, BK=32, 4 warps (128 thr), warp tile 32x32 (2 mtiles x 4 ntiles of 16x8).
// A: [M,K] row-major (stride lda).
// TRANSB=false: B[K,N] row-major (ldb). TRANSB=true: B[N,K] row-major (ldb).
// epi 0: C = acc + bias
// epi 1: C = tanhf(acc + bias)
// epi 2: C += (acc + bias) * (hstep_base[m*257]/3)    (Euler, in place)
// Smem holds tiles in MMA-fragment order: each lane's A-frag = 1 LDS.128, B-frag = 1 LDS.64.
template <bool TRANSB>
__global__ __launch_bounds__(128)
void gemm_tc(const float* __restrict__ A, int lda,
             const float* __restrict__ B, int ldb,
             const float* __restrict__ bias,
             float* __restrict__ C, int ldc,
             int K, int epi, const float* __restrict__ hstep_base)
{
    // frag layout: As[mtile(4)][kk(4)][lane(32)][reg(4)], Bs[ntile(8)][kk(4)][lane(32)][reg(2)]
    __shared__ float As[4 * 4 * 32 * 4];   // 8 KB
    __shared__ float Bs[8 * 4 * 32 * 2];   // 8 KB

    const int tid  = threadIdx.x;
    const int lane = tid & 31;
    const int w    = tid >> 5;
    const int warp_m = w & 1;    // 2 mtiles each (rows)
    const int warp_n = w >> 1;   // 4 ntiles each (cols)
    const int bm = blockIdx.y * 64;
    const int bn = blockIdx.x * 64;

    float acc[2][4][4];
#pragma unroll
    for (int i = 0; i < 2; i++)
#pragma unroll
        for (int j = 0; j < 4; j++)
#pragma unroll
            for (int r = 0; r < 4; r++) acc[i][j][r] = 0.0f;

    float ra[16], rb[16];

    // --- register-staged global loads (16 A elems + 16 B elems per thread) ---
    auto loadA = [&](int k0) {
#pragma unroll
        for (int i = 0; i < 16; i++) {
            int e = tid + i * 128;
            int m = e >> 5, k = e & 31;
            ra[i] = A[(size_t)(bm + m) * lda + (k0 + k)];
        }
    };
    auto loadB = [&](int k0) {
#pragma unroll
        for (int i = 0; i < 16; i++) {
            int e = tid + i * 128;
            if (!TRANSB) {
                int k = e >> 6, n = e & 63;
                rb[i] = B[(size_t)(k0 + k) * ldb + (bn + n)];
            } else {
                int n = e >> 5, k = e & 31;
                rb[i] = B[(size_t)(bn + n) * ldb + (k0 + k)];
            }
        }
    };
    // --- scatter to fragment-order smem (with tf32 rounding) ---
    auto storeA = [&]() {
#pragma unroll
        for (int i = 0; i < 16; i++) {
            int e = tid + i * 128;
            int m = e >> 5, k = e & 31;
            int mtile = m >> 4, mm = m & 15;
            int kk = k >> 3, c8 = k & 7;
            int ln  = (mm & 7) * 4 + (c8 & 3);
            int reg = ((mm >> 3) & 1) + 2 * ((c8 >> 2) & 1);
            As[(((mtile * 4 + kk) * 32) + ln) * 4 + reg] = to_tf32(ra[i]);
        }
    };
    auto storeB = [&]() {
#pragma unroll
        for (int i = 0; i < 16; i++) {
            int e = tid + i * 128;
            int k, n;
            if (!TRANSB) { k = e >> 6; n = e & 63; }
            else         { n = e >> 5; k = e & 31; }
            int ntile = n >> 3, nn = n & 7;
            int kk = k >> 3, k8 = k & 7;
            int ln  = nn * 4 + (k8 & 3);
            int reg = (k8 >> 2) & 1;
            Bs[(((ntile * 4 + kk) * 32) + ln) * 2 + reg] = to_tf32(rb[i]);
        }
    };

    loadA(0); loadB(0);
    const int nk = K >> 5;
    for (int it = 0; it < nk; it++) {
        storeA(); storeB();
        __syncthreads();
        if (it + 1 < nk) { loadA((it + 1) << 5); loadB((it + 1) << 5); }  // overlap next loads with MMA

#pragma unroll
        for (int kk = 0; kk < 4; kk++) {
            uint32_t a[2][4], b[4][2];
#pragma unroll
            for (int i = 0; i < 2; i++) {
                int mtile = warp_m * 2 + i;
                float4 v = *reinterpret_cast<const float4*>(&As[(((mtile * 4 + kk) * 32) + lane) * 4]);
                a[i][0] = __float_as_uint(v.x); a[i][1] = __float_as_uint(v.y);
                a[i][2] = __float_as_uint(v.z); a[i][3] = __float_as_uint(v.w);
            }
#pragma unroll
            for (int j = 0; j < 4; j++) {
                int ntile = warp_n * 4 + j;
                float2 v = *reinterpret_cast<const float2*>(&Bs[(((ntile * 4 + kk) * 32) + lane) * 2]);
                b[j][0] = __float_as_uint(v.x); b[j][1] = __float_as_uint(v.y);
            }
#pragma unroll
            for (int i = 0; i < 2; i++)
#pragma unroll
                for (int j = 0; j < 4; j++)
                    mma_tf32(acc[i][j][0], acc[i][j][1], acc[i][j][2], acc[i][j][3],
                             a[i][0], a[i][1], a[i][2], a[i][3], b[j][0], b[j][1]);
        }
        __syncthreads();
    }

    // ---------------- epilogue ----------------
    const int gid = lane >> 2;       // groupID
    const int tig = lane & 3;        // thread-in-group
#pragma unroll
    for (int i = 0; i < 2; i++) {
        int r0 = bm + (warp_m * 2 + i) * 16 + gid;   // rows r0, r0+8
#pragma unroll
        for (int j = 0; j < 4; j++) {
            int c0 = bn + (warp_n * 4 + j) * 8 + tig * 2;   // cols c0, c0+1
            float bv0 = bias[c0], bv1 = bias[c0 + 1];
            float v00 = acc[i][j][0] + bv0, v01 = acc[i][j][1] + bv1;
            float v10 = acc[i][j][2] + bv0, v11 = acc[i][j][3] + bv1;
            float* p0 = C + (size_t)r0 * ldc + c0;
            float* p1 = C + (size_t)(r0 + 8) * ldc + c0;
            if (epi == 0) {
                p0[0] = v00; p0[1] = v01; p1[0] = v10; p1[1] = v11;
            } else if (epi == 1) {
                p0[0] = tanhf(v00); p0[1] = tanhf(v01);
                p1[0] = tanhf(v10); p1[1] = tanhf(v11);
            } else {
                float h0 = hstep_base[r0 * ROWSTRIDE]       * (1.0f / 3.0f);
                float h1 = hstep_base[(r0 + 8) * ROWSTRIDE] * (1.0f / 3.0f);
                p0[0] += v00 * h0; p0[1] += v01 * h0;
                p1[0] += v10 * h1; p1[1] += v11 * h1;
            }
        }
    }
}

// ---------------- GRU gates + carry update + output ----------------
__global__ __launch_bounds__(1024)
void gate_k(const float* __restrict__ gi, const float* __restrict__ gh,
            const float* __restrict__ cur, float* __restrict__ nxt,
            float* __restrict__ out_seq, float* __restrict__ out_tail)
{
    int m = blockIdx.x;
    int j = threadIdx.x;   // 0..1023
    size_t base = (size_t)m * G3;

    float gr = gi[base + j]       + gh[base + j];
    float gz = gi[base + HID + j] + gh[base + HID + j];
    float r  = 1.0f / (1.0f + expf(-gr));
    float z  = 1.0f / (1.0f + expf(-gz));
    float n  = tanhf(gi[base + 2 * HID + j] + r * gh[base + 2 * HID + j]);
    float h  = cur[m * HID + j];
    float nh = (1.0f - z) * n + z * h;

    out_tail[m * HID + j] = nh;                 // last step's write survives
    if (j < LAT) {
        out_seq[m * LAT + j] = nh;              // ode_states_post[t]
        nxt[m * HID + j]       = nh;            // next ode_state
        nxt[m * HID + LAT + j] = nh;            // next gru_state
    }
}

__global__ void zero_k(float* __restrict__ p, int n)
{
    int i = blockIdx.x * blockDim.x + threadIdx.x;
    if (i < n) p[i] = 0.0f;
}

// ---------------- launch ----------------
extern "C" void kernel_launch(void* const* d_in, const int* in_sizes, int n_in,
                              void* d_out, int out_size)
{
    const float* data = (const float*)d_in[0];   // (50, 256, 257)
    const float* w1   = (const float*)d_in[1];   // (512, 1024)
    const float* b1   = (const float*)d_in[2];   // (1024,)
    const float* w2   = (const float*)d_in[3];   // (1024, 512)
    const float* b2   = (const float*)d_in[4];   // (512,)
    const float* wih  = (const float*)d_in[5];   // (3072, 256)
    const float* bih  = (const float*)d_in[6];   // (3072,)
    const float* whh  = (const float*)d_in[7];   // (3072, 1024)
    const float* bhh  = (const float*)d_in[8];   // (3072,)

    float* out      = (float*)d_out;
    float* out_tail = out + (size_t)LSEQ * BATCH * LAT;

    float *act, *hcatA, *hcatB, *gh, *gi;
    cudaGetSymbolAddress((void**)&act,   g_act);
    cudaGetSymbolAddress((void**)&hcatA, g_hcatA);
    cudaGetSymbolAddress((void**)&hcatB, g_hcatB);
    cudaGetSymbolAddress((void**)&gh,    g_gh);
    cudaGetSymbolAddress((void**)&gi,    g_gi);

    // zero-init carry (every replay)
    zero_k<<<(BATCH * HID + 255) / 256, 256>>>(hcatA, BATCH * HID);

    // Precompute gi for ALL steps: [12800,256] x Wih^T -> [12800,3072]
    {
        dim3 grid(G3 / 64, (LSEQ * BATCH) / 64);   // (48, 200)
        gemm_tc<true><<<grid, 128>>>(data, ROWSTRIDE, wih, DIN, bih, gi, G3, DIN, 0, nullptr);
    }

    for (int t = 0; t < LSEQ; t++) {
        float* cur = (t & 1) ? hcatB : hcatA;
        float* nxt = (t & 1) ? hcatA : hcatB;
        const float* hstep = data + (size_t)t * BATCH * ROWSTRIDE + DIN;

        // 3 Euler substeps: y (= cur[:, :512], in place)
        for (int s = 0; s < 3; s++) {
            dim3 g1(HODE / 64, BATCH / 64);    // (16, 4)
            gemm_tc<false><<<g1, 128>>>(cur, HID, w1, HODE, b1, act, HODE, LAT, 1, nullptr);
            dim3 g2(LAT / 64, BATCH / 64);     // (8, 4)
            gemm_tc<false><<<g2, 128>>>(act, HODE, w2, LAT, b2, cur, HID, HODE, 2, hstep);
        }

        // gh = hcat @ Whh^T + bhh   [256,1024] x [3072,1024]^T
        {
            dim3 g4(G3 / 64, BATCH / 64);      // (48, 4)
            gemm_tc<true><<<g4, 128>>>(cur, HID, whh, HID, bhh, gh, G3, HID, 0, nullptr);
        }

        // gates + carry + outputs
        gate_k<<<BATCH, HID>>>(gi + (size_t)t * BATCH * G3, gh, cur, nxt,
                               out + (size_t)t * BATCH * LAT, out_tail);
    }
}